// round 6
// baseline (speedup 1.0000x reference)
#include <cuda_runtime.h>
#include <math.h>

#define NLV 16
#define LOG2T 19
#define TMASK ((1u << LOG2T) - 1u)
#define P1 2654435761u
#define P2 805459861u

#define NBUCKET (1 << 15)      // 32^3 Morton buckets (~30 pts/bucket ~= 1 warp)
#define MAXN (1 << 20)

__device__ int g_hist[NBUCKET];   // zero at kernel_launch entry (invariant, restored by scan)
__device__ int g_off[NBUCKET];
__device__ float4 g_xs[MAXN];     // sorted coords + original index

struct LP {
    float g[NLV];   // grid = 2/res
    float ig[NLV];  // 1/grid = res/2
};

// ---------- Morton bucketing (5 bits/axis) ----------
__device__ __forceinline__ unsigned spread3(unsigned v) {
    v &= 0x3FF;
    v = (v | (v << 16)) & 0x030000FF;
    v = (v | (v << 8))  & 0x0300F00F;
    v = (v | (v << 4))  & 0x030C30C3;
    v = (v | (v << 2))  & 0x09249249;
    return v;
}

__device__ __forceinline__ unsigned morton_key(float xx, float xy, float xz) {
    float px = fminf(fmaxf(xx, -1.0f), 1.0f) + 1.0f;  // [0,2]
    float py = fminf(fmaxf(xy, -1.0f), 1.0f) + 1.0f;
    float pz = fminf(fmaxf(xz, -1.0f), 1.0f) + 1.0f;
    unsigned ix = min(31u, (unsigned)(px * 16.0f));
    unsigned iy = min(31u, (unsigned)(py * 16.0f));
    unsigned iz = min(31u, (unsigned)(pz * 16.0f));
    return (spread3(ix) << 2) | (spread3(iy) << 1) | spread3(iz);
}

// 4 points per thread, vectorized x reads (12 floats = 3x float4, 48B-aligned).
__global__ void hist_kernel(const float4* __restrict__ x4, int N) {
    int base = (blockIdx.x * 256 + threadIdx.x) * 4;
    if (base >= N) return;
    float4 q0 = __ldg(x4 + (size_t)base * 3 / 4 + 0);
    float4 q1 = __ldg(x4 + (size_t)base * 3 / 4 + 1);
    float4 q2 = __ldg(x4 + (size_t)base * 3 / 4 + 2);
    float c[12] = {q0.x,q0.y,q0.z,q0.w, q1.x,q1.y,q1.z,q1.w, q2.x,q2.y,q2.z,q2.w};
#pragma unroll
    for (int k = 0; k < 4; k++) {
        if (base + k < N)
            atomicAdd(&g_hist[morton_key(c[3*k], c[3*k+1], c[3*k+2])], 1);
    }
}

// Single-block exclusive scan over 32768 bins; resets g_hist.
__global__ void __launch_bounds__(1024) scan_kernel() {
    int t = threadIdx.x;
    int a[32];
    int4* src = (int4*)g_hist + t * 8;
#pragma unroll
    for (int j = 0; j < 8; j++) {
        int4 q = src[j];
        a[4*j+0] = q.x; a[4*j+1] = q.y; a[4*j+2] = q.z; a[4*j+3] = q.w;
    }
    int tot = 0;
#pragma unroll
    for (int k = 0; k < 32; k++) { int v = a[k]; a[k] = tot; tot += v; }

    int lane = t & 31, w = t >> 5;
    int s = tot;
#pragma unroll
    for (int d = 1; d < 32; d <<= 1) {
        int u = __shfl_up_sync(0xFFFFFFFFu, s, d);
        if (lane >= d) s += u;
    }
    __shared__ int wsum[32];
    if (lane == 31) wsum[w] = s;
    __syncthreads();
    if (w == 0) {
        int v = wsum[lane];
        int ss = v;
#pragma unroll
        for (int d = 1; d < 32; d <<= 1) {
            int u = __shfl_up_sync(0xFFFFFFFFu, ss, d);
            if (lane >= d) ss += u;
        }
        wsum[lane] = ss - v;
    }
    __syncthreads();
    int excl = (s - tot) + wsum[w];

    int4* dst = (int4*)g_off + t * 8;
    int4 z = make_int4(0, 0, 0, 0);
#pragma unroll
    for (int j = 0; j < 8; j++) {
        dst[j] = make_int4(a[4*j+0] + excl, a[4*j+1] + excl,
                           a[4*j+2] + excl, a[4*j+3] + excl);
        src[j] = z;   // reset g_hist
    }
}

// 4 points per thread: claim rank via atomic, stage sorted coords.
__global__ void scatter_kernel(const float4* __restrict__ x4, int N) {
    int base = (blockIdx.x * 256 + threadIdx.x) * 4;
    if (base >= N) return;
    float4 q0 = __ldg(x4 + (size_t)base * 3 / 4 + 0);
    float4 q1 = __ldg(x4 + (size_t)base * 3 / 4 + 1);
    float4 q2 = __ldg(x4 + (size_t)base * 3 / 4 + 2);
    float c[12] = {q0.x,q0.y,q0.z,q0.w, q1.x,q1.y,q1.z,q1.w, q2.x,q2.y,q2.z,q2.w};
    int pos[4];
#pragma unroll
    for (int k = 0; k < 4; k++) {
        if (base + k < N)
            pos[k] = atomicAdd(&g_off[morton_key(c[3*k], c[3*k+1], c[3*k+2])], 1);
    }
#pragma unroll
    for (int k = 0; k < 4; k++) {
        if (base + k < N)
            g_xs[pos[k]] = make_float4(c[3*k], c[3*k+1], c[3*k+2],
                                       __int_as_float(base + k));
    }
}

// ---------- main encoder (R4 math, smem-coalesced output) ----------
__global__ void __launch_bounds__(256)
ingp_hash_kernel(const float* __restrict__ x,
                 const float2* __restrict__ emb,
                 float4* __restrict__ out,
                 int N, LP lp, int use_sorted)
{
    __shared__ float4 s_res[256][9];  // [thread][pair], padded: 4-phase-optimal
    __shared__ int s_n[256];

    int i = blockIdx.x * 256 + threadIdx.x;
    bool active = (i < N);

    int n = 0;
    float xx = 0.f, xy = 0.f, xz = 0.f;
    if (active) {
        if (use_sorted) {
            float4 v = __ldg(g_xs + i);
            xx = v.x; xy = v.y; xz = v.z;
            n = __float_as_int(v.w);
        } else {
            n = i;
            xx = __ldg(x + 3 * n + 0);
            xy = __ldg(x + 3 * n + 1);
            xz = __ldg(x + 3 * n + 2);
        }
    }
    s_n[threadIdx.x] = active ? n : -1;

    float px = fminf(fmaxf(xx, -1.0f), 1.0f) + 1.0f;
    float py = fminf(fmaxf(xy, -1.0f), 1.0f) + 1.0f;
    float pz = fminf(fmaxf(xz, -1.0f), 1.0f) + 1.0f;

    float2 prev = make_float2(0.0f, 0.0f);

#pragma unroll
    for (int l = 0; l < NLV; l++) {
        const float2* __restrict__ t = emb + ((size_t)l << LOG2T);
        float g  = lp.g[l];
        float ig = lp.ig[l];

        int bx = __float2int_rd(px * ig);
        int by = __float2int_rd(py * ig);
        int bz = __float2int_rd(pz * ig);
        float wx = fmaf(-(float)bx, g, px) * ig;
        float wy = fmaf(-(float)by, g, py) * ig;
        float wz = fmaf(-(float)bz, g, pz) * ig;

        unsigned hx0 = (unsigned)bx;
        unsigned hx1 = hx0 + 1u;
        unsigned hy0 = (unsigned)by * P1;
        unsigned hy1 = hy0 + P1;
        unsigned hz0 = (unsigned)bz * P2;
        unsigned hz1 = hz0 + P2;

        unsigned a00 = hx0 ^ hy0;
        unsigned a01 = hx0 ^ hy1;
        unsigned a10 = hx1 ^ hy0;
        unsigned a11 = hx1 ^ hy1;

        float2 e000 = __ldg(t + ((a00 ^ hz0) & TMASK));
        float2 e001 = __ldg(t + ((a00 ^ hz1) & TMASK));
        float2 e010 = __ldg(t + ((a01 ^ hz0) & TMASK));
        float2 e011 = __ldg(t + ((a01 ^ hz1) & TMASK));
        float2 e100 = __ldg(t + ((a10 ^ hz0) & TMASK));
        float2 e101 = __ldg(t + ((a10 ^ hz1) & TMASK));
        float2 e110 = __ldg(t + ((a11 ^ hz0) & TMASK));
        float2 e111 = __ldg(t + ((a11 ^ hz1) & TMASK));

        float ux = 1.0f - wx;
        float uy = 1.0f - wy;
        float uz = 1.0f - wz;

        float s00 = uy * uz;
        float s01 = uy * wz;
        float s10 = wy * uz;
        float s11 = wy * wz;

        float w000 = ux * s00, w001 = ux * s01, w010 = ux * s10, w011 = ux * s11;
        float w100 = wx * s00, w101 = wx * s01, w110 = wx * s10, w111 = wx * s11;

        float rx = w000 * e000.x;
        float ry = w000 * e000.y;
        rx = fmaf(w001, e001.x, rx); ry = fmaf(w001, e001.y, ry);
        rx = fmaf(w010, e010.x, rx); ry = fmaf(w010, e010.y, ry);
        rx = fmaf(w011, e011.x, rx); ry = fmaf(w011, e011.y, ry);
        rx = fmaf(w100, e100.x, rx); ry = fmaf(w100, e100.y, ry);
        rx = fmaf(w101, e101.x, rx); ry = fmaf(w101, e101.y, ry);
        rx = fmaf(w110, e110.x, rx); ry = fmaf(w110, e110.y, ry);
        rx = fmaf(w111, e111.x, rx); ry = fmaf(w111, e111.y, ry);

        if (l & 1) {
            s_res[threadIdx.x][l >> 1] = make_float4(prev.x, prev.y, rx, ry);
        } else {
            prev.x = rx;
            prev.y = ry;
        }
    }

    __syncthreads();

    // Coalesced writeout: 8 lanes cover one point's contiguous 128B row.
    int c = threadIdx.x & 7;
    int pbase = threadIdx.x >> 3;   // 0..31
#pragma unroll
    for (int k = 0; k < 8; k++) {
        int p = pbase + k * 32;
        int pn = s_n[p];
        if (pn >= 0) {
            __stcs(out + (size_t)pn * 8 + c, s_res[p][c]);
        }
    }
}

extern "C" void kernel_launch(void* const* d_in, const int* in_sizes, int n_in,
                              void* d_out, int out_size)
{
    const float*  x   = (const float*)d_in[0];
    const float2* emb = (const float2*)d_in[1];
    int N = in_sizes[0] / 3;

    LP lp;
    double b = exp((log(512.0) - log(16.0)) / 15.0);
    for (int l = 0; l < NLV; l++) {
        float r = (float)floor(16.0 * pow(b, (double)l));
        lp.g[l]  = 2.0f / r;
        lp.ig[l] = r * 0.5f;
    }

    int blocks = (N + 255) / 256;
    if (blocks <= 0) return;

    // N*3 floats must be float4-addressable for the x4 kernels (N multiple of 4).
    if (N <= MAXN && (N & 3) == 0) {
        int qblocks = (N / 4 + 255) / 256;
        hist_kernel<<<qblocks, 256>>>((const float4*)x, N);
        scan_kernel<<<1, 1024>>>();
        scatter_kernel<<<qblocks, 256>>>((const float4*)x, N);
        ingp_hash_kernel<<<blocks, 256>>>(x, emb, (float4*)d_out, N, lp, 1);
    } else {
        ingp_hash_kernel<<<blocks, 256>>>(x, emb, (float4*)d_out, N, lp, 0);
    }
}

// round 7
// speedup vs baseline: 2.0348x; 2.0348x over previous
#include <cuda_runtime.h>
#include <math.h>

#define NLV 16
#define LOG2T 19
#define TMASK ((1u << LOG2T) - 1u)
#define P1 2654435761u
#define P2 805459861u

#define NBUCKET (1 << 18)      // 64^3 Morton buckets (~30 pts/bucket ~= 1 warp)
#define MAXN (1 << 20)
#define SCAN_BLOCKS 256        // NBUCKET / 1024

__device__ int g_hist[NBUCKET];   // zero at kernel_launch entry (invariant, restored by scan_apply)
__device__ int g_off[NBUCKET];
__device__ int g_bsum[SCAN_BLOCKS];
__device__ float4 g_xs[MAXN];     // sorted coords + original index

struct LP {
    float g[NLV];   // grid = 2/res
    float ig[NLV];  // 1/grid = res/2
};

// ---------- Morton bucketing (6 bits/axis) ----------
__device__ __forceinline__ unsigned spread3(unsigned v) {
    v &= 0x3FF;
    v = (v | (v << 16)) & 0x030000FF;
    v = (v | (v << 8))  & 0x0300F00F;
    v = (v | (v << 4))  & 0x030C30C3;
    v = (v | (v << 2))  & 0x09249249;
    return v;
}

__device__ __forceinline__ unsigned morton_key(float xx, float xy, float xz) {
    float px = fminf(fmaxf(xx, -1.0f), 1.0f) + 1.0f;  // [0,2]
    float py = fminf(fmaxf(xy, -1.0f), 1.0f) + 1.0f;
    float pz = fminf(fmaxf(xz, -1.0f), 1.0f) + 1.0f;
    unsigned ix = min(63u, (unsigned)(px * 32.0f));
    unsigned iy = min(63u, (unsigned)(py * 32.0f));
    unsigned iz = min(63u, (unsigned)(pz * 32.0f));
    return (spread3(ix) << 2) | (spread3(iy) << 1) | spread3(iz);
}

// 4 points per thread, vectorized x reads (12 floats = 3x float4).
__global__ void hist_kernel(const float4* __restrict__ x4, int N) {
    int base = (blockIdx.x * 256 + threadIdx.x) * 4;
    if (base >= N) return;
    float4 q0 = __ldg(x4 + (size_t)base * 3 / 4 + 0);
    float4 q1 = __ldg(x4 + (size_t)base * 3 / 4 + 1);
    float4 q2 = __ldg(x4 + (size_t)base * 3 / 4 + 2);
    float c[12] = {q0.x,q0.y,q0.z,q0.w, q1.x,q1.y,q1.z,q1.w, q2.x,q2.y,q2.z,q2.w};
#pragma unroll
    for (int k = 0; k < 4; k++) {
        if (base + k < N)
            atomicAdd(&g_hist[morton_key(c[3*k], c[3*k+1], c[3*k+2])], 1);
    }
}

// Block totals of g_hist: 256 blocks x 1024 threads.
__global__ void __launch_bounds__(1024) reduce_kernel() {
    int gid = blockIdx.x * 1024 + threadIdx.x;
    int v = g_hist[gid];
    int lane = threadIdx.x & 31, w = threadIdx.x >> 5;
#pragma unroll
    for (int d = 16; d >= 1; d >>= 1) v += __shfl_down_sync(0xFFFFFFFFu, v, d);
    __shared__ int part[32];
    if (lane == 0) part[w] = v;
    __syncthreads();
    if (w == 0) {
        int t = part[lane];
#pragma unroll
        for (int d = 16; d >= 1; d >>= 1) t += __shfl_down_sync(0xFFFFFFFFu, t, d);
        if (lane == 0) g_bsum[blockIdx.x] = t;
    }
}

// Exclusive scan: each block scans its 1024 elems locally, computes its global
// prefix by summing g_bsum[0..bid) itself, writes g_off, resets g_hist.
__global__ void __launch_bounds__(1024) scan_apply_kernel() {
    int bid = blockIdx.x;
    int gid = bid * 1024 + threadIdx.x;
    int v = g_hist[gid];
    g_hist[gid] = 0;

    int lane = threadIdx.x & 31, w = threadIdx.x >> 5;

    __shared__ int wsum[32];
    __shared__ int part[8];
    __shared__ int s_pre;

    int s = v;
#pragma unroll
    for (int d = 1; d < 32; d <<= 1) {
        int t = __shfl_up_sync(0xFFFFFFFFu, s, d);
        if (lane >= d) s += t;
    }
    if (lane == 31) wsum[w] = s;

    if (threadIdx.x < 256) {
        int t = (threadIdx.x < bid) ? g_bsum[threadIdx.x] : 0;
#pragma unroll
        for (int d = 16; d >= 1; d >>= 1) t += __shfl_down_sync(0xFFFFFFFFu, t, d);
        if (lane == 0) part[threadIdx.x >> 5] = t;
    }
    __syncthreads();

    if (w == 0) {
        int t = wsum[lane];
        int ss = t;
#pragma unroll
        for (int d = 1; d < 32; d <<= 1) {
            int u = __shfl_up_sync(0xFFFFFFFFu, ss, d);
            if (lane >= d) ss += u;
        }
        wsum[lane] = ss - t;
    }
    if (threadIdx.x == 512) {
        int t = 0;
#pragma unroll
        for (int i = 0; i < 8; i++) t += part[i];
        s_pre = t;
    }
    __syncthreads();

    g_off[gid] = (s - v) + wsum[w] + s_pre;
}

// 4 points per thread: claim rank via atomic, stage sorted coords.
__global__ void scatter_kernel(const float4* __restrict__ x4, int N) {
    int base = (blockIdx.x * 256 + threadIdx.x) * 4;
    if (base >= N) return;
    float4 q0 = __ldg(x4 + (size_t)base * 3 / 4 + 0);
    float4 q1 = __ldg(x4 + (size_t)base * 3 / 4 + 1);
    float4 q2 = __ldg(x4 + (size_t)base * 3 / 4 + 2);
    float c[12] = {q0.x,q0.y,q0.z,q0.w, q1.x,q1.y,q1.z,q1.w, q2.x,q2.y,q2.z,q2.w};
    int pos[4];
#pragma unroll
    for (int k = 0; k < 4; k++) {
        if (base + k < N)
            pos[k] = atomicAdd(&g_off[morton_key(c[3*k], c[3*k+1], c[3*k+2])], 1);
    }
#pragma unroll
    for (int k = 0; k < 4; k++) {
        if (base + k < N)
            g_xs[pos[k]] = make_float4(c[3*k], c[3*k+1], c[3*k+2],
                                       __int_as_float(base + k));
    }
}

// ---------- main encoder (R4 version: zero smem, direct stores) ----------
__global__ void __launch_bounds__(256)
ingp_hash_kernel(const float* __restrict__ x,
                 const float2* __restrict__ emb,
                 float4* __restrict__ out,
                 int N, LP lp, int use_sorted)
{
    int i = blockIdx.x * 256 + threadIdx.x;
    if (i >= N) return;

    int n;
    float xx, xy, xz;
    if (use_sorted) {
        float4 v = __ldg(g_xs + i);
        xx = v.x; xy = v.y; xz = v.z;
        n = __float_as_int(v.w);
    } else {
        n = i;
        xx = __ldg(x + 3 * n + 0);
        xy = __ldg(x + 3 * n + 1);
        xz = __ldg(x + 3 * n + 2);
    }

    float px = fminf(fmaxf(xx, -1.0f), 1.0f) + 1.0f;
    float py = fminf(fmaxf(xy, -1.0f), 1.0f) + 1.0f;
    float pz = fminf(fmaxf(xz, -1.0f), 1.0f) + 1.0f;

    float2 prev = make_float2(0.0f, 0.0f);

#pragma unroll
    for (int l = 0; l < NLV; l++) {
        const float2* __restrict__ t = emb + ((size_t)l << LOG2T);
        float g  = lp.g[l];
        float ig = lp.ig[l];

        int bx = __float2int_rd(px * ig);
        int by = __float2int_rd(py * ig);
        int bz = __float2int_rd(pz * ig);
        float wx = fmaf(-(float)bx, g, px) * ig;
        float wy = fmaf(-(float)by, g, py) * ig;
        float wz = fmaf(-(float)bz, g, pz) * ig;

        unsigned hx0 = (unsigned)bx;
        unsigned hx1 = hx0 + 1u;
        unsigned hy0 = (unsigned)by * P1;
        unsigned hy1 = hy0 + P1;
        unsigned hz0 = (unsigned)bz * P2;
        unsigned hz1 = hz0 + P2;

        unsigned a00 = hx0 ^ hy0;
        unsigned a01 = hx0 ^ hy1;
        unsigned a10 = hx1 ^ hy0;
        unsigned a11 = hx1 ^ hy1;

        float2 e000 = __ldg(t + ((a00 ^ hz0) & TMASK));
        float2 e001 = __ldg(t + ((a00 ^ hz1) & TMASK));
        float2 e010 = __ldg(t + ((a01 ^ hz0) & TMASK));
        float2 e011 = __ldg(t + ((a01 ^ hz1) & TMASK));
        float2 e100 = __ldg(t + ((a10 ^ hz0) & TMASK));
        float2 e101 = __ldg(t + ((a10 ^ hz1) & TMASK));
        float2 e110 = __ldg(t + ((a11 ^ hz0) & TMASK));
        float2 e111 = __ldg(t + ((a11 ^ hz1) & TMASK));

        float ux = 1.0f - wx;
        float uy = 1.0f - wy;
        float uz = 1.0f - wz;

        float s00 = uy * uz;
        float s01 = uy * wz;
        float s10 = wy * uz;
        float s11 = wy * wz;

        float w000 = ux * s00, w001 = ux * s01, w010 = ux * s10, w011 = ux * s11;
        float w100 = wx * s00, w101 = wx * s01, w110 = wx * s10, w111 = wx * s11;

        float rx = w000 * e000.x;
        float ry = w000 * e000.y;
        rx = fmaf(w001, e001.x, rx); ry = fmaf(w001, e001.y, ry);
        rx = fmaf(w010, e010.x, rx); ry = fmaf(w010, e010.y, ry);
        rx = fmaf(w011, e011.x, rx); ry = fmaf(w011, e011.y, ry);
        rx = fmaf(w100, e100.x, rx); ry = fmaf(w100, e100.y, ry);
        rx = fmaf(w101, e101.x, rx); ry = fmaf(w101, e101.y, ry);
        rx = fmaf(w110, e110.x, rx); ry = fmaf(w110, e110.y, ry);
        rx = fmaf(w111, e111.x, rx); ry = fmaf(w111, e111.y, ry);

        if (l & 1) {
            float4 v = make_float4(prev.x, prev.y, rx, ry);
            __stcs(out + (size_t)n * 8 + (l >> 1), v);
        } else {
            prev.x = rx;
            prev.y = ry;
        }
    }
}

extern "C" void kernel_launch(void* const* d_in, const int* in_sizes, int n_in,
                              void* d_out, int out_size)
{
    const float*  x   = (const float*)d_in[0];
    const float2* emb = (const float2*)d_in[1];
    int N = in_sizes[0] / 3;

    LP lp;
    double b = exp((log(512.0) - log(16.0)) / 15.0);
    for (int l = 0; l < NLV; l++) {
        float r = (float)floor(16.0 * pow(b, (double)l));
        lp.g[l]  = 2.0f / r;
        lp.ig[l] = r * 0.5f;
    }

    int blocks = (N + 255) / 256;
    if (blocks <= 0) return;

    if (N <= MAXN && (N & 3) == 0) {
        int qblocks = (N / 4 + 255) / 256;
        hist_kernel<<<qblocks, 256>>>((const float4*)x, N);
        reduce_kernel<<<SCAN_BLOCKS, 1024>>>();
        scan_apply_kernel<<<SCAN_BLOCKS, 1024>>>();
        scatter_kernel<<<qblocks, 256>>>((const float4*)x, N);
        ingp_hash_kernel<<<blocks, 256>>>(x, emb, (float4*)d_out, N, lp, 1);
    } else {
        ingp_hash_kernel<<<blocks, 256>>>(x, emb, (float4*)d_out, N, lp, 0);
    }
}